// round 2
// baseline (speedup 1.0000x reference)
#include <cuda_runtime.h>
#include <cuda_bf16.h>

#define N_NODES 100000
#define IN_CH   256
#define HID     64
#define E_EDGES 1200000
#define HALF    (N_NODES/2)

// Scratch (no allocations allowed). 16B-aligned for float4 / vector atomics.
__device__ __align__(16) float g_h[N_NODES * HID];     // h = x @ W
__device__ __align__(16) float g_agg[N_NODES * HID];   // segment-sum accumulator

// ---------------------------------------------------------------------------
// Kernel 0: zero the accumulator (must happen every replay)
// ---------------------------------------------------------------------------
__global__ void zero_agg_kernel() {
    int i = blockIdx.x * blockDim.x + threadIdx.x;
    int n4 = (N_NODES * HID) / 4;
    if (i < n4) {
        reinterpret_cast<float4*>(g_agg)[i] = make_float4(0.f, 0.f, 0.f, 0.f);
    }
}

// ---------------------------------------------------------------------------
// Kernel 1: h = x @ W   (100000x256 @ 256x64, fp32)
// Block tile: 128 rows x 64 cols, K-chunks of 64.
// 256 threads, each computes an 8-row x 4-col microtile (32 accumulators).
// Shared: Xs 128x64 f32 (32KB) + Ws 64x64 f32 (16KB) = 48KB.
// ---------------------------------------------------------------------------
__global__ __launch_bounds__(256) void gemm_kernel(const float* __restrict__ x,
                                                   const float* __restrict__ W) {
    __shared__ float Xs[128][64];
    __shared__ float Ws[64][64];

    const int tid = threadIdx.x;
    const int tx  = tid & 15;       // col group: cols tx*4 .. tx*4+3
    const int ty  = tid >> 4;       // row group: rows ty*8 .. ty*8+7
    const int rowBase = blockIdx.x * 128;

    float acc[8][4];
    #pragma unroll
    for (int r = 0; r < 8; r++)
        #pragma unroll
        for (int c = 0; c < 4; c++) acc[r][c] = 0.f;

    for (int kc = 0; kc < IN_CH / 64; kc++) {
        // Stage Xs: 128 rows x 64 k-vals = 2048 float4 slots, 8 per thread.
        #pragma unroll
        for (int i = 0; i < 8; i++) {
            int s  = tid + i * 256;       // 0..2047
            int r  = s >> 4;              // row within tile
            int kq = s & 15;              // float4 index within 64-k chunk
            int grow = rowBase + r;
            float4 v = make_float4(0.f, 0.f, 0.f, 0.f);
            if (grow < N_NODES)
                v = *reinterpret_cast<const float4*>(&x[(size_t)grow * IN_CH + kc * 64 + kq * 4]);
            Xs[r][kq * 4 + 0] = v.x;
            Xs[r][kq * 4 + 1] = v.y;
            Xs[r][kq * 4 + 2] = v.z;
            Xs[r][kq * 4 + 3] = v.w;
        }
        // Stage Ws: 64 k x 64 cols = 1024 float4 slots, 4 per thread.
        #pragma unroll
        for (int i = 0; i < 4; i++) {
            int s = tid + i * 256;        // 0..1023
            int k = s >> 4;
            int j = s & 15;
            *reinterpret_cast<float4*>(&Ws[k][j * 4]) =
                *reinterpret_cast<const float4*>(&W[(size_t)(kc * 64 + k) * HID + j * 4]);
        }
        __syncthreads();

        #pragma unroll 16
        for (int k = 0; k < 64; k++) {
            float4 wf = *reinterpret_cast<float4*>(&Ws[k][tx * 4]);
            #pragma unroll
            for (int r = 0; r < 8; r++) {
                float xv = Xs[ty * 8 + r][k];
                acc[r][0] += xv * wf.x;
                acc[r][1] += xv * wf.y;
                acc[r][2] += xv * wf.z;
                acc[r][3] += xv * wf.w;
            }
        }
        __syncthreads();
    }

    #pragma unroll
    for (int r = 0; r < 8; r++) {
        int grow = rowBase + ty * 8 + r;
        if (grow < N_NODES) {
            *reinterpret_cast<float4*>(&g_h[(size_t)grow * HID + tx * 4]) =
                make_float4(acc[r][0], acc[r][1], acc[r][2], acc[r][3]);
        }
    }
}

// ---------------------------------------------------------------------------
// Kernel 2: scatter-add  agg[dst] += h[src] * w
// edge_index arrives as int32 (harness downcasts int64 inputs).
// 16 threads per edge, each handles one float4 of the 64 channels.
// ---------------------------------------------------------------------------
__global__ __launch_bounds__(256) void scatter_kernel(const int* __restrict__ ei,
                                                      const float* __restrict__ ew) {
    long long idx = (long long)blockIdx.x * blockDim.x + threadIdx.x;
    int e  = (int)(idx >> 4);
    int c4 = (int)(idx & 15) * 4;
    if (e >= E_EDGES) return;

    int src = ei[e];
    int dst = ei[E_EDGES + e];
    if ((unsigned)src >= N_NODES || (unsigned)dst >= N_NODES) return;  // defensive
    float w = ew[e];

    float4 v = *reinterpret_cast<const float4*>(&g_h[(size_t)src * HID + c4]);
    float4 m = make_float4(v.x * w, v.y * w, v.z * w, v.w * w);

    atomicAdd(reinterpret_cast<float4*>(&g_agg[(size_t)dst * HID + c4]), m);
}

// ---------------------------------------------------------------------------
// Kernel 3: epilogue — bias + PReLU + concat(act[:half], act[half:], axis=1)
// out[i, j] : j<64 -> act[i][j] ; j>=64 -> act[i+HALF][j-64]
// ---------------------------------------------------------------------------
__global__ void epilogue_kernel(const float* __restrict__ b,
                                const float* __restrict__ pa,
                                float* __restrict__ out) {
    int i = blockIdx.x * blockDim.x + threadIdx.x;   // float4 index over output
    int n4 = (HALF * 128) / 4;
    if (i >= n4) return;
    int o   = i * 4;
    int row = o >> 7;          // / 128
    int j   = o & 127;
    int n   = (j < 64) ? row : row + HALF;
    int c   = j & 63;

    float4 v  = *reinterpret_cast<const float4*>(&g_agg[(size_t)n * HID + c]);
    float4 bb = *reinterpret_cast<const float4*>(&b[c]);
    float4 aa = *reinterpret_cast<const float4*>(&pa[c]);

    v.x += bb.x; v.y += bb.y; v.z += bb.z; v.w += bb.w;
    v.x = (v.x > 0.f) ? v.x : aa.x * v.x;
    v.y = (v.y > 0.f) ? v.y : aa.y * v.y;
    v.z = (v.z > 0.f) ? v.z : aa.z * v.z;
    v.w = (v.w > 0.f) ? v.w : aa.w * v.w;

    *reinterpret_cast<float4*>(&out[o]) = v;
}

// ---------------------------------------------------------------------------
extern "C" void kernel_launch(void* const* d_in, const int* in_sizes, int n_in,
                              void* d_out, int out_size) {
    const float* x  = (const float*)d_in[0];
    const int*   ei = (const int*)d_in[1];
    const float* ew = (const float*)d_in[2];
    const float* W  = (const float*)d_in[3];
    const float* b  = (const float*)d_in[4];
    const float* pa = (const float*)d_in[5];
    float* out = (float*)d_out;

    int zeroBlocks = ((N_NODES * HID) / 4 + 255) / 256;
    zero_agg_kernel<<<zeroBlocks, 256>>>();

    int gemmBlocks = (N_NODES + 127) / 128;
    gemm_kernel<<<gemmBlocks, 256>>>(x, W);

    long long scatterThreads = (long long)E_EDGES * 16;
    int scatterBlocks = (int)((scatterThreads + 255) / 256);
    scatter_kernel<<<scatterBlocks, 256>>>(ei, ew);

    int epiBlocks = ((HALF * 128) / 4 + 255) / 256;
    epilogue_kernel<<<epiBlocks, 256>>>(b, pa, out);
}

// round 3
// speedup vs baseline: 1.2469x; 1.2469x over previous
#include <cuda_runtime.h>
#include <cuda_bf16.h>

#define N_NODES 100000
#define N_PAD   100096            // 391 blocks * 256 rows
#define IN_CH   256
#define HID     64
#define E_EDGES 1200000
#define HALF    (N_NODES/2)

#define BM 256                    // block row tile
#define KC 32                     // k chunk
#define XS 40                     // padded shared stride (bf16) for X tiles
#define WS 40                     // padded shared stride (bf16) for W tiles

// Scratch (no allocations allowed). Padded so block-granular writes need no guards.
__device__ __align__(16) float g_h[N_PAD * HID];
__device__ __align__(16) float g_agg[N_PAD * HID];

// ---------------------------------------------------------------------------
// mma / ldmatrix helpers
// ---------------------------------------------------------------------------
__device__ __forceinline__ void mma_bf16(float* c, const unsigned* a, const unsigned* b) {
    asm volatile(
        "mma.sync.aligned.m16n8k16.row.col.f32.bf16.bf16.f32 "
        "{%0,%1,%2,%3}, {%4,%5,%6,%7}, {%8,%9}, {%0,%1,%2,%3};\n"
        : "+f"(c[0]), "+f"(c[1]), "+f"(c[2]), "+f"(c[3])
        : "r"(a[0]), "r"(a[1]), "r"(a[2]), "r"(a[3]), "r"(b[0]), "r"(b[1]));
}

__device__ __forceinline__ void ldsm_x4(unsigned* d, const __nv_bfloat16* p) {
    unsigned addr = (unsigned)__cvta_generic_to_shared(p);
    asm volatile("ldmatrix.sync.aligned.m8n8.x4.shared.b16 {%0,%1,%2,%3}, [%4];\n"
                 : "=r"(d[0]), "=r"(d[1]), "=r"(d[2]), "=r"(d[3]) : "r"(addr));
}

__device__ __forceinline__ void split2(float v, __nv_bfloat16& h, __nv_bfloat16& l) {
    h = __float2bfloat16_rn(v);
    l = __float2bfloat16_rn(v - __bfloat162float(h));
}

// ---------------------------------------------------------------------------
// Kernel 1: h = x @ W (tensor cores, bf16 3-term split) + zero g_agg slice
// Block: 256 rows x 64 cols. 8 warps, each warp a 32x64 tile (2 m-subtiles).
// ---------------------------------------------------------------------------
extern __shared__ __nv_bfloat16 sm_dyn[];

__global__ __launch_bounds__(256) void gemm_kernel(const float* __restrict__ x,
                                                   const float* __restrict__ W) {
    __nv_bfloat16* Xhi = sm_dyn;                 // [BM][XS]
    __nv_bfloat16* Xlo = Xhi + BM * XS;          // [BM][XS]
    __nv_bfloat16* Wh  = Xlo + BM * XS;          // [64][WS]  (transposed: [n][k])
    __nv_bfloat16* Wl  = Wh  + 64 * WS;          // [64][WS]

    const int tid  = threadIdx.x;
    const int warp = tid >> 5;
    const int lane = tid & 31;
    const int rowBase = blockIdx.x * BM;

    // Fused: zero this block's g_agg slice (256 rows x 64 cols = 4096 float4)
    {
        float4* dst = reinterpret_cast<float4*>(&g_agg[(size_t)rowBase * HID]);
        #pragma unroll
        for (int i = 0; i < 16; i++)
            dst[tid + i * 256] = make_float4(0.f, 0.f, 0.f, 0.f);
    }

    float acc[2][8][4];
    #pragma unroll
    for (int mt = 0; mt < 2; mt++)
        #pragma unroll
        for (int nt = 0; nt < 8; nt++)
            #pragma unroll
            for (int q = 0; q < 4; q++) acc[mt][nt][q] = 0.f;

    const int g = lane >> 3;       // ldmatrix quadrant
    const int r = lane & 7;

    for (int kb = 0; kb < IN_CH; kb += KC) {
        // ---- Stage X chunk: 256 rows x 32 k (2048 float4, 8 per thread) ----
        #pragma unroll
        for (int i = 0; i < 8; i++) {
            int s   = tid + i * 256;
            int row = s >> 3;            // 8 float4 per row
            int q   = s & 7;
            int grow = rowBase + row;
            float4 v = make_float4(0.f, 0.f, 0.f, 0.f);
            if (grow < N_NODES)
                v = *reinterpret_cast<const float4*>(&x[(size_t)grow * IN_CH + kb + q * 4]);
            __nv_bfloat16 h0, l0, h1, l1, h2, l2, h3, l3;
            split2(v.x, h0, l0); split2(v.y, h1, l1);
            split2(v.z, h2, l2); split2(v.w, h3, l3);
            int base = row * XS + q * 4;
            Xhi[base+0]=h0; Xhi[base+1]=h1; Xhi[base+2]=h2; Xhi[base+3]=h3;
            Xlo[base+0]=l0; Xlo[base+1]=l1; Xlo[base+2]=l2; Xlo[base+3]=l3;
        }
        // ---- Stage W chunk transposed: 32 k x 64 n -> Wh/Wl[n][k] ----
        #pragma unroll
        for (int i = 0; i < 2; i++) {
            int s = tid + i * 256;       // 0..511 float4 slots
            int k = s >> 4;              // 0..31
            int n = (s & 15) * 4;
            float4 v = *reinterpret_cast<const float4*>(&W[(size_t)(kb + k) * HID + n]);
            __nv_bfloat16 hh, ll;
            split2(v.x, hh, ll); Wh[(n+0)*WS + k] = hh; Wl[(n+0)*WS + k] = ll;
            split2(v.y, hh, ll); Wh[(n+1)*WS + k] = hh; Wl[(n+1)*WS + k] = ll;
            split2(v.z, hh, ll); Wh[(n+2)*WS + k] = hh; Wl[(n+2)*WS + k] = ll;
            split2(v.w, hh, ll); Wh[(n+3)*WS + k] = hh; Wl[(n+3)*WS + k] = ll;
        }
        __syncthreads();

        // ---- Compute: 2 k16-steps per chunk ----
        #pragma unroll
        for (int ks = 0; ks < 2; ks++) {
            const int kk = ks * 16;
            // A fragments (2 m-subtiles, hi+lo)
            unsigned ah[2][4], al[2][4];
            #pragma unroll
            for (int mt = 0; mt < 2; mt++) {
                int arow = warp * 32 + mt * 16 + (g & 1) * 8 + r;
                int acol = kk + (g >> 1) * 8;
                ldsm_x4(ah[mt], &Xhi[arow * XS + acol]);
                ldsm_x4(al[mt], &Xlo[arow * XS + acol]);
            }
            // B fragments per n-tile pair; mma
            #pragma unroll
            for (int nt2 = 0; nt2 < 4; nt2++) {
                unsigned bh[4], bl[4];
                int brow = nt2 * 16 + (g >> 1) * 8 + r;  // n-index row in Wh/Wl
                int bcol = kk + (g & 1) * 8;
                ldsm_x4(bh, &Wh[brow * WS + bcol]);
                ldsm_x4(bl, &Wl[brow * WS + bcol]);
                #pragma unroll
                for (int mt = 0; mt < 2; mt++) {
                    mma_bf16(acc[mt][2*nt2],   ah[mt], &bh[0]);
                    mma_bf16(acc[mt][2*nt2],   ah[mt], &bl[0]);
                    mma_bf16(acc[mt][2*nt2],   al[mt], &bh[0]);
                    mma_bf16(acc[mt][2*nt2+1], ah[mt], &bh[2]);
                    mma_bf16(acc[mt][2*nt2+1], ah[mt], &bl[2]);
                    mma_bf16(acc[mt][2*nt2+1], al[mt], &bh[2]);
                }
            }
        }
        __syncthreads();
    }

    // ---- Store h (g_h padded; rows >= N_NODES write harmless zeros) ----
    const int crow = lane >> 2;
    const int ccol = (lane & 3) * 2;
    #pragma unroll
    for (int mt = 0; mt < 2; mt++) {
        int row0 = rowBase + warp * 32 + mt * 16 + crow;
        #pragma unroll
        for (int nt = 0; nt < 8; nt++) {
            int col = nt * 8 + ccol;
            *reinterpret_cast<float2*>(&g_h[(size_t)row0 * HID + col]) =
                make_float2(acc[mt][nt][0], acc[mt][nt][1]);
            *reinterpret_cast<float2*>(&g_h[(size_t)(row0 + 8) * HID + col]) =
                make_float2(acc[mt][nt][2], acc[mt][nt][3]);
        }
    }
}

// ---------------------------------------------------------------------------
// Kernel 2: scatter-add  agg[dst] += h[src] * w   (16 threads/edge, float4 RED)
// ---------------------------------------------------------------------------
__global__ __launch_bounds__(256) void scatter_kernel(const int* __restrict__ ei,
                                                      const float* __restrict__ ew) {
    long long idx = (long long)blockIdx.x * blockDim.x + threadIdx.x;
    int e  = (int)(idx >> 4);
    int c4 = (int)(idx & 15) * 4;
    if (e >= E_EDGES) return;

    int src = ei[e];
    int dst = ei[E_EDGES + e];
    float w = ew[e];

    float4 v = *reinterpret_cast<const float4*>(&g_h[(size_t)src * HID + c4]);
    float4 m = make_float4(v.x * w, v.y * w, v.z * w, v.w * w);

    atomicAdd(reinterpret_cast<float4*>(&g_agg[(size_t)dst * HID + c4]), m);
}

// ---------------------------------------------------------------------------
// Kernel 3: epilogue — bias + PReLU + concat(act[:half], act[half:], axis=1)
// ---------------------------------------------------------------------------
__global__ void epilogue_kernel(const float* __restrict__ b,
                                const float* __restrict__ pa,
                                float* __restrict__ out) {
    int i = blockIdx.x * blockDim.x + threadIdx.x;
    int n4 = (HALF * 128) / 4;
    if (i >= n4) return;
    int o   = i * 4;
    int row = o >> 7;
    int j   = o & 127;
    int n   = (j < 64) ? row : row + HALF;
    int c   = j & 63;

    float4 v  = *reinterpret_cast<const float4*>(&g_agg[(size_t)n * HID + c]);
    float4 bb = *reinterpret_cast<const float4*>(&b[c]);
    float4 aa = *reinterpret_cast<const float4*>(&pa[c]);

    v.x += bb.x; v.y += bb.y; v.z += bb.z; v.w += bb.w;
    v.x = (v.x > 0.f) ? v.x : aa.x * v.x;
    v.y = (v.y > 0.f) ? v.y : aa.y * v.y;
    v.z = (v.z > 0.f) ? v.z : aa.z * v.z;
    v.w = (v.w > 0.f) ? v.w : aa.w * v.w;

    *reinterpret_cast<float4*>(&out[o]) = v;
}

// ---------------------------------------------------------------------------
extern "C" void kernel_launch(void* const* d_in, const int* in_sizes, int n_in,
                              void* d_out, int out_size) {
    const float* x  = (const float*)d_in[0];
    const int*   ei = (const int*)d_in[1];
    const float* ew = (const float*)d_in[2];
    const float* W  = (const float*)d_in[3];
    const float* b  = (const float*)d_in[4];
    const float* pa = (const float*)d_in[5];
    float* out = (float*)d_out;

    const int smem = (2 * BM * XS + 2 * 64 * WS) * (int)sizeof(__nv_bfloat16);  // 51200
    static bool attr_set = false;
    if (!attr_set) {
        cudaFuncSetAttribute(gemm_kernel, cudaFuncAttributeMaxDynamicSharedMemorySize, smem);
        attr_set = true;
    }

    int gemmBlocks = (N_NODES + BM - 1) / BM;     // 391
    gemm_kernel<<<gemmBlocks, 256, smem>>>(x, W);

    long long scatterThreads = (long long)E_EDGES * 16;
    int scatterBlocks = (int)((scatterThreads + 255) / 256);
    scatter_kernel<<<scatterBlocks, 256>>>(ei, ew);

    int epiBlocks = ((HALF * 128) / 4 + 255) / 256;
    epilogue_kernel<<<epiBlocks, 256>>>(b, pa, out);
}

// round 5
// speedup vs baseline: 1.2586x; 1.0094x over previous
#include <cuda_runtime.h>
#include <cuda_bf16.h>
#include <cstdint>

#define N_NODES 100000
#define N_PAD   100096            // 782 blocks * 128 rows
#define IN_CH   256
#define HID     64
#define E_EDGES 1200000
#define HALF    (N_NODES/2)

#define BM 128                    // rows per block
#define KC 32                     // k chunk
#define XS 40                     // padded smem stride (bf16)
#define WS 40

// Scratch (no allocations allowed). Padded so block-granular writes need no guards.
__device__ __align__(16) float g_h[N_PAD * HID];
__device__ __align__(16) float g_agg[N_PAD * HID];

// ---------------------------------------------------------------------------
__device__ __forceinline__ void mma_bf16(float* c, const unsigned* a, const unsigned* b) {
    asm volatile(
        "mma.sync.aligned.m16n8k16.row.col.f32.bf16.bf16.f32 "
        "{%0,%1,%2,%3}, {%4,%5,%6,%7}, {%8,%9}, {%0,%1,%2,%3};\n"
        : "+f"(c[0]), "+f"(c[1]), "+f"(c[2]), "+f"(c[3])
        : "r"(a[0]), "r"(a[1]), "r"(a[2]), "r"(a[3]), "r"(b[0]), "r"(b[1]));
}

__device__ __forceinline__ void ldsm_x4(unsigned* d, const __nv_bfloat16* p) {
    unsigned addr = (unsigned)__cvta_generic_to_shared(p);
    asm volatile("ldmatrix.sync.aligned.m8n8.x4.shared.b16 {%0,%1,%2,%3}, [%4];\n"
                 : "=r"(d[0]), "=r"(d[1]), "=r"(d[2]), "=r"(d[3]) : "r"(addr));
}

__device__ __forceinline__ void split2(float v, __nv_bfloat16& h, __nv_bfloat16& l) {
    h = __float2bfloat16_rn(v);
    l = __float2bfloat16_rn(v - __bfloat162float(h));
}

// ---------------------------------------------------------------------------
// Kernel 1: h = x @ W (mma.sync bf16 3-term split), software-pipelined,
// fused g_agg zeroing. Block: 128 rows x 64 cols, 8 warps, warp tile 16x64.
// ---------------------------------------------------------------------------
__global__ __launch_bounds__(256) void gemm_kernel(const float* __restrict__ x,
                                                   const float* __restrict__ W) {
    __shared__ __nv_bfloat16 Xhi[BM][XS];
    __shared__ __nv_bfloat16 Xlo[BM][XS];
    __shared__ __nv_bfloat16 Wh[64][WS];   // transposed: [n][k]
    __shared__ __nv_bfloat16 Wl[64][WS];

    const int tid  = threadIdx.x;
    const int warp = tid >> 5;
    const int lane = tid & 31;
    const int rowBase = blockIdx.x * BM;

    // Fused: zero this block's g_agg slice (128 rows x 64 = 2048 float4)
    {
        float4* dst = reinterpret_cast<float4*>(&g_agg[(size_t)rowBase * HID]);
        #pragma unroll
        for (int i = 0; i < 8; i++)
            dst[tid + i * 256] = make_float4(0.f, 0.f, 0.f, 0.f);
    }

    float acc[8][4];
    #pragma unroll
    for (int nt = 0; nt < 8; nt++)
        #pragma unroll
        for (int q = 0; q < 4; q++) acc[nt][q] = 0.f;

    // Prefetch registers: X chunk = 128x32 f32 = 1024 float4 (4/thread),
    // W chunk = 32x64 = 512 float4 (2/thread).
    float4 rx[4];
    float4 rw[2];

    const int xrow = tid >> 3;          // (tid + i*256) >> 3 pattern flattened below
    const int g = lane >> 3;
    const int r = lane & 7;

    // ---- load chunk kb into prefetch regs ----
    auto load_chunk = [&](int kb) {
        #pragma unroll
        for (int i = 0; i < 4; i++) {
            int s   = tid + i * 256;
            int row = s >> 3;
            int q   = s & 7;
            int grow = rowBase + row;
            rx[i] = (grow < N_NODES)
                ? *reinterpret_cast<const float4*>(&x[(size_t)grow * IN_CH + kb + q * 4])
                : make_float4(0.f, 0.f, 0.f, 0.f);
        }
        #pragma unroll
        for (int i = 0; i < 2; i++) {
            int s = tid + i * 256;
            int k = s >> 4;
            int n = (s & 15) * 4;
            rw[i] = *reinterpret_cast<const float4*>(&W[(size_t)(kb + k) * HID + n]);
        }
    };

    // ---- convert prefetch regs into smem ----
    auto store_chunk = [&]() {
        #pragma unroll
        for (int i = 0; i < 4; i++) {
            int s   = tid + i * 256;
            int row = s >> 3;
            int q   = s & 7;
            __nv_bfloat16 h0,l0,h1,l1,h2,l2,h3,l3;
            split2(rx[i].x, h0, l0); split2(rx[i].y, h1, l1);
            split2(rx[i].z, h2, l2); split2(rx[i].w, h3, l3);
            Xhi[row][q*4+0]=h0; Xhi[row][q*4+1]=h1; Xhi[row][q*4+2]=h2; Xhi[row][q*4+3]=h3;
            Xlo[row][q*4+0]=l0; Xlo[row][q*4+1]=l1; Xlo[row][q*4+2]=l2; Xlo[row][q*4+3]=l3;
        }
        #pragma unroll
        for (int i = 0; i < 2; i++) {
            int s = tid + i * 256;
            int k = s >> 4;
            int n = (s & 15) * 4;
            float vv[4] = {rw[i].x, rw[i].y, rw[i].z, rw[i].w};
            #pragma unroll
            for (int j = 0; j < 4; j++) {
                __nv_bfloat16 hh, ll;
                split2(vv[j], hh, ll);
                Wh[n + j][k] = hh;
                Wl[n + j][k] = ll;
            }
        }
    };

    load_chunk(0);

    for (int kc = 0; kc < IN_CH / KC; kc++) {
        store_chunk();
        __syncthreads();

        if (kc + 1 < IN_CH / KC) load_chunk((kc + 1) * KC);   // LDGs overlap mma below

        #pragma unroll
        for (int ks = 0; ks < 2; ks++) {
            const int kk = ks * 16;
            unsigned ah[4], al[4];
            int arow = warp * 16 + (g & 1) * 8 + r;
            int acol = kk + (g >> 1) * 8;
            ldsm_x4(ah, &Xhi[arow][acol]);
            ldsm_x4(al, &Xlo[arow][acol]);
            #pragma unroll
            for (int nt2 = 0; nt2 < 4; nt2++) {
                unsigned bh[4], bl[4];
                int brow = nt2 * 16 + (g >> 1) * 8 + r;
                int bcol = kk + (g & 1) * 8;
                ldsm_x4(bh, &Wh[brow][bcol]);
                ldsm_x4(bl, &Wl[brow][bcol]);
                mma_bf16(acc[2*nt2],   ah, &bh[0]);
                mma_bf16(acc[2*nt2],   ah, &bl[0]);
                mma_bf16(acc[2*nt2],   al, &bh[0]);
                mma_bf16(acc[2*nt2+1], ah, &bh[2]);
                mma_bf16(acc[2*nt2+1], ah, &bl[2]);
                mma_bf16(acc[2*nt2+1], al, &bh[2]);
            }
        }
        __syncthreads();
    }

    // ---- Store h (g_h padded; rows >= N_NODES write harmless garbage zeros) ----
    const int crow = lane >> 2;
    const int ccol = (lane & 3) * 2;
    int row0 = rowBase + warp * 16 + crow;
    #pragma unroll
    for (int nt = 0; nt < 8; nt++) {
        int col = nt * 8 + ccol;
        *reinterpret_cast<float2*>(&g_h[(size_t)row0 * HID + col]) =
            make_float2(acc[nt][0], acc[nt][1]);
        *reinterpret_cast<float2*>(&g_h[(size_t)(row0 + 8) * HID + col]) =
            make_float2(acc[nt][2], acc[nt][3]);
    }
    (void)xrow;
}

// ---------------------------------------------------------------------------
// Kernel 2: scatter-add  agg[dst] += h[src] * w   (16 threads/edge, float4 RED)
// ---------------------------------------------------------------------------
__global__ __launch_bounds__(256) void scatter_kernel(const int* __restrict__ ei,
                                                      const float* __restrict__ ew) {
    long long idx = (long long)blockIdx.x * blockDim.x + threadIdx.x;
    int e  = (int)(idx >> 4);
    int c4 = (int)(idx & 15) * 4;
    if (e >= E_EDGES) return;

    int src = ei[e];
    int dst = ei[E_EDGES + e];
    float w = ew[e];

    float4 v = *reinterpret_cast<const float4*>(&g_h[(size_t)src * HID + c4]);
    float4 m = make_float4(v.x * w, v.y * w, v.z * w, v.w * w);

    atomicAdd(reinterpret_cast<float4*>(&g_agg[(size_t)dst * HID + c4]), m);
}

// ---------------------------------------------------------------------------
// Kernel 3: epilogue — bias + PReLU + concat(act[:half], act[half:], axis=1)
// ---------------------------------------------------------------------------
__global__ void epilogue_kernel(const float* __restrict__ b,
                                const float* __restrict__ pa,
                                float* __restrict__ out) {
    int i = blockIdx.x * blockDim.x + threadIdx.x;
    int n4 = (HALF * 128) / 4;
    if (i >= n4) return;
    int o   = i * 4;
    int row = o >> 7;
    int j   = o & 127;
    int n   = (j < 64) ? row : row + HALF;
    int c   = j & 63;

    float4 v  = *reinterpret_cast<const float4*>(&g_agg[(size_t)n * HID + c]);
    float4 bb = *reinterpret_cast<const float4*>(&b[c]);
    float4 aa = *reinterpret_cast<const float4*>(&pa[c]);

    v.x += bb.x; v.y += bb.y; v.z += bb.z; v.w += bb.w;
    v.x = (v.x > 0.f) ? v.x : aa.x * v.x;
    v.y = (v.y > 0.f) ? v.y : aa.y * v.y;
    v.z = (v.z > 0.f) ? v.z : aa.z * v.z;
    v.w = (v.w > 0.f) ? v.w : aa.w * v.w;

    *reinterpret_cast<float4*>(&out[o]) = v;
}

// ---------------------------------------------------------------------------
extern "C" void kernel_launch(void* const* d_in, const int* in_sizes, int n_in,
                              void* d_out, int out_size) {
    const float* x  = (const float*)d_in[0];
    const int*   ei = (const int*)d_in[1];
    const float* ew = (const float*)d_in[2];
    const float* W  = (const float*)d_in[3];
    const float* b  = (const float*)d_in[4];
    const float* pa = (const float*)d_in[5];
    float* out = (float*)d_out;

    int gemmBlocks = N_PAD / BM;                  // 782
    gemm_kernel<<<gemmBlocks, 256>>>(x, W);

    long long scatterThreads = (long long)E_EDGES * 16;
    int scatterBlocks = (int)((scatterThreads + 255) / 256);
    scatter_kernel<<<scatterBlocks, 256>>>(ei, ew);

    int epiBlocks = ((HALF * 128) / 4 + 255) / 256;
    epilogue_kernel<<<epiBlocks, 256>>>(b, pa, out);
}